// round 2
// baseline (speedup 1.0000x reference)
#include <cuda_runtime.h>

// Chunk-local reverse inclusive cumsum with scale fusion.
//   g: [B, T, H] f32, BT=64 chunks along T, H=64.
//   out[b, c, t, h] = SCALE * sum_{s >= t} g[b, c, s, h]
//
// Mapping: one thread per (chunk, h-quad). Loads are explicitly batched
// UNROLL=16 deep into registers to expose MLP against DRAM latency; the
// serial suffix-sum chain then runs over registers. Fully coalesced
// LDG.128 / STG.128 per warp. Pure streaming: read once, write once.

static constexpr int BT = 64;
static constexpr int H  = 64;
static constexpr int HQ = H / 4;          // float4 quads per row = 16
static constexpr int UNROLL = 16;         // float4 loads batched per group
static constexpr float SCALE = 0.5f;

__global__ __launch_bounds__(128)
void rev_cumsum_kernel(const float4* __restrict__ g,
                       float4* __restrict__ out,
                       int n_cols)  // total (chunk, h-quad) columns
{
    int tid = blockIdx.x * blockDim.x + threadIdx.x;
    if (tid >= n_cols) return;

    int hq    = tid & (HQ - 1);           // 0..15
    int chunk = tid >> 4;                 // global chunk index

    size_t base = (size_t)chunk * (BT * HQ) + hq;
    const float4* __restrict__ gp = g   + base;
    float4*       __restrict__ op = out + base;

    float4 run = make_float4(0.f, 0.f, 0.f, 0.f);

    #pragma unroll
    for (int grp = BT / UNROLL - 1; grp >= 0; --grp) {
        // Batch-issue UNROLL independent 128-bit loads (front-batched MLP).
        float4 v[UNROLL];
        #pragma unroll
        for (int j = 0; j < UNROLL; ++j)
            v[j] = gp[(grp * UNROLL + j) * HQ];

        // Serial suffix-sum over the register batch; stores are
        // fire-and-forget.
        #pragma unroll
        for (int j = UNROLL - 1; j >= 0; --j) {
            run.x += v[j].x;
            run.y += v[j].y;
            run.z += v[j].z;
            run.w += v[j].w;
            float4 o;
            o.x = run.x * SCALE;
            o.y = run.y * SCALE;
            o.z = run.z * SCALE;
            o.w = run.w * SCALE;
            op[(grp * UNROLL + j) * HQ] = o;
        }
    }
}

extern "C" void kernel_launch(void* const* d_in, const int* in_sizes, int n_in,
                              void* d_out, int out_size)
{
    const float4* g   = (const float4*)d_in[0];
    float4*       out = (float4*)d_out;

    int total_elems = in_sizes[0];            // B * T * H
    int n_cols = total_elems / (BT * H) * HQ; // chunks * h-quads

    int threads = 128;
    int blocks  = (n_cols + threads - 1) / threads;
    rev_cumsum_kernel<<<blocks, threads>>>(g, out, n_cols);
}

// round 3
// speedup vs baseline: 1.1723x; 1.1723x over previous
#include <cuda_runtime.h>

// Chunk-local reverse inclusive cumsum with scale fusion.
//   g: [B, T, H] f32, BT=64 chunks along T, H=64.
//   out[b, c, t, h] = SCALE * sum_{s >= t} g[b, c, s, h]
//
// Mapping: one thread per (chunk, head-pair). float2 granularity doubles the
// thread count vs float4 (131072 threads -> ~28 warps/SM) to cover DRAM
// latency; loads are batched UNROLL=16 deep into registers (32 data regs,
// cheap enough for ptxas to actually keep in flight). Per warp each t-step
// touches 256 contiguous bytes: fully coalesced. Read once, write once.

static constexpr int BT = 64;
static constexpr int H  = 64;
static constexpr int HP = H / 2;          // float2 pairs per row = 32
static constexpr int UNROLL = 16;         // float2 loads batched per group
static constexpr float SCALE = 0.5f;

__global__ __launch_bounds__(128)
void rev_cumsum_kernel(const float2* __restrict__ g,
                       float2* __restrict__ out,
                       int n_cols)  // total (chunk, head-pair) columns
{
    int tid = blockIdx.x * blockDim.x + threadIdx.x;
    if (tid >= n_cols) return;

    int hp    = tid & (HP - 1);           // 0..31
    int chunk = tid >> 5;                 // global chunk index

    size_t base = (size_t)chunk * (BT * HP) + hp;
    const float2* __restrict__ gp = g   + base;
    float2*       __restrict__ op = out + base;

    float rx = 0.f, ry = 0.f;

    #pragma unroll
    for (int grp = BT / UNROLL - 1; grp >= 0; --grp) {
        // Batch-issue UNROLL independent 64-bit loads (front-batched MLP).
        float2 v[UNROLL];
        #pragma unroll
        for (int j = 0; j < UNROLL; ++j)
            v[j] = gp[(grp * UNROLL + j) * HP];

        // Serial suffix-sum over the register batch.
        #pragma unroll
        for (int j = UNROLL - 1; j >= 0; --j) {
            rx += v[j].x;
            ry += v[j].y;
            float2 o;
            o.x = rx * SCALE;
            o.y = ry * SCALE;
            op[(grp * UNROLL + j) * HP] = o;
        }
    }
}

extern "C" void kernel_launch(void* const* d_in, const int* in_sizes, int n_in,
                              void* d_out, int out_size)
{
    const float2* g   = (const float2*)d_in[0];
    float2*       out = (float2*)d_out;

    int total_elems = in_sizes[0];            // B * T * H
    int n_cols = total_elems / (BT * H) * HP; // chunks * head-pairs

    int threads = 128;
    int blocks  = (n_cols + threads - 1) / threads;
    rev_cumsum_kernel<<<blocks, threads>>>(g, out, n_cols);
}